// round 14
// baseline (speedup 1.0000x reference)
#include <cuda_runtime.h>
#include <math.h>

// Problem constants
#define BTT     16
#define NM      1024
#define NL      64
#define NKV     1088
#define DIMM    128
#define HEADS   8
#define INNER   2048
#define QSCALE  0.08838834764831845f   // 128^-0.5
#define KVHALF  544

// Static device scratch
static __device__ float  g_pp[2 * 4 * 8 * DIMM * DIMM];       // split-K prep partials
static __device__ float  g_po[2 * BTT * HEADS * NL * DIMM];   // un-normalized O halves
static __device__ float2 g_ml2[2 * BTT * HEADS * NL];         // (m, l) per half per row

// fp32 -> tf32 round-to-nearest
__device__ __forceinline__ float cf(float x){
    unsigned u; asm("cvt.rna.tf32.f32 %0, %1;" : "=r"(u) : "f"(x));
    return __uint_as_float(u);
}
__device__ __forceinline__ unsigned uu(float x){ return __float_as_uint(x); }

__device__ __forceinline__ void mma8(float* d, const unsigned* a, const unsigned* b){
    asm volatile("mma.sync.aligned.m16n8k8.row.col.f32.tf32.tf32.f32 "
        "{%0,%1,%2,%3}, {%4,%5,%6,%7}, {%8,%9}, {%0,%1,%2,%3};"
        : "+f"(d[0]), "+f"(d[1]), "+f"(d[2]), "+f"(d[3])
        : "r"(a[0]), "r"(a[1]), "r"(a[2]), "r"(a[3]), "r"(b[0]), "r"(b[1]));
}

// row r of concat(tensor[bt], latents[bt])
__device__ __forceinline__ const float* row_ptr(
    const float* __restrict__ tensor, const float* __restrict__ latents, int bt, int r)
{
    return (r < NM) ? tensor  + ((size_t)bt * NM + r)        * DIMM
                    : latents + ((size_t)bt * NL + (r - NM)) * DIMM;
}

// sum 4 split-K slices (same order as the old prep_red: ((s0+s1)+s2)+s3) * alpha
__device__ __forceinline__ float4 sum4m(
    const float* __restrict__ p0, const float* __restrict__ p1,
    const float* __restrict__ p2, const float* __restrict__ p3,
    size_t off, float alpha)
{
    float4 a = *(const float4*)(p0 + off);
    float4 b = *(const float4*)(p1 + off);
    float4 c = *(const float4*)(p2 + off);
    float4 d = *(const float4*)(p3 + off);
    float4 r;
    r.x = (((a.x + b.x) + c.x) + d.x) * alpha;
    r.y = (((a.y + b.y) + c.y) + d.y) * alpha;
    r.z = (((a.z + b.z) + c.z) + d.z) * alpha;
    r.w = (((a.w + b.w) + c.w) + d.w) * alpha;
    return r;
}

#define BSW 4352   // words per B staging buffer (32*136)

// full-width fragment step: warp tile 16x64
__device__ __forceinline__ void frag_full(
    const float* __restrict__ At, const float* __restrict__ Bs,
    float acc[8][4], int wm, int wn, int grp, int qid, int akbase)
{
    #pragma unroll
    for (int kk = 0; kk < 32; kk += 8) {
        unsigned a[4], b[8][2];
        const int k0 = akbase + kk;
        a[0] = uu(At[(k0+qid  )*72 + wm+grp  ]);
        a[1] = uu(At[(k0+qid  )*72 + wm+grp+8]);
        a[2] = uu(At[(k0+qid+4)*72 + wm+grp  ]);
        a[3] = uu(At[(k0+qid+4)*72 + wm+grp+8]);
        #pragma unroll
        for (int j = 0; j < 8; j++) {
            b[j][0] = uu(Bs[(kk+qid  )*136 + wn+8*j+grp]);
            b[j][1] = uu(Bs[(kk+qid+4)*136 + wn+8*j+grp]);
        }
        #pragma unroll
        for (int j = 0; j < 8; j++) mma8(acc[j], a, b[j]);
    }
}

// half-width fragment step: warp tile 16x32 (S phase)
__device__ __forceinline__ void frag_half(
    const float* __restrict__ At, const float* __restrict__ Bs,
    float acc[4][4], int wm, int wn2, int grp, int qid, int akbase)
{
    #pragma unroll
    for (int kk = 0; kk < 32; kk += 8) {
        unsigned a[4], b[4][2];
        const int k0 = akbase + kk;
        a[0] = uu(At[(k0+qid  )*72 + wm+grp  ]);
        a[1] = uu(At[(k0+qid  )*72 + wm+grp+8]);
        a[2] = uu(At[(k0+qid+4)*72 + wm+grp  ]);
        a[3] = uu(At[(k0+qid+4)*72 + wm+grp+8]);
        #pragma unroll
        for (int j = 0; j < 4; j++) {
            b[j][0] = uu(Bs[(kk+qid  )*136 + wn2+8*j+grp]);
            b[j][1] = uu(Bs[(kk+qid+4)*136 + wn2+8*j+grp]);
        }
        #pragma unroll
        for (int j = 0; j < 4; j++) mma8(acc[j], a, b[j]);
    }
}

// ===========================================================================
// k_flash (R13 structure): grid 128 = (bt, head-pair, kv-half), 512 threads.
// Warps 0-7 = head A, 8-15 = head B; KV tiles staged ONCE per pair.
// QW B-staging now sums the 4 g_pp M-slices on the fly (x QSCALE) — the
// values are bit-identical to the old prep_red output.
// ===========================================================================
#define FLASH_WORDS (2*9216 + 2*9216 + 4*BSW + 384)
#define FLASH_SMEM  (FLASH_WORDS * 4)   // 218624 bytes

__global__ void __launch_bounds__(512, 1) k_flash(
    const float* __restrict__ tensor, const float* __restrict__ latents)
{
    extern __shared__ float sm[];
    const int zz = blockIdx.x;                 // 0..127
    const int half = zz & 1, hp = (zz >> 1) & 3, bt = zz >> 3;
    const int kvbase = half * KVHALF;

    const int t = threadIdx.x, warp = t >> 5, lane = t & 31;
    const int head = warp >> 3, w8 = warp & 7;
    const int grp = lane >> 2, qid = lane & 3;
    const int wm  = (w8 & 3) * 16;
    const int wn  = (w8 >> 2) * 64;
    const int wn2 = (w8 >> 2) * 32;
    const int hglob = hp * 2 + head;

    float* QWt   = sm + head * 9216;           // [128 dims][72]
    float* LATt  = sm + 18432;                 // latents transposed (shared; = SXt of head0)
    float* SXt   = sm + 18432 + head * 9216;   // scores/P [kv][72] per head
    float* BsAll = sm + 36864;                 // 4 x [32][136]
    float* stats = sm + 36864 + 4*BSW;         // m[128] | l[128] | rsc[128]
    float* rsc   = stats + 256 + head * 64;

    if (t < 128) { stats[t] = -INFINITY; stats[128 + t] = 0.f; }

    // stage latents[bt] (64x128) transposed -> LATt (shared by both heads)
    {
        const int r = t >> 3, k0 = (t & 7) * 16;
        const float* Lp = latents + (size_t)bt * NL * DIMM + (size_t)r * DIMM + k0;
        #pragma unroll
        for (int i = 0; i < 4; i++) {
            float4 v = *(const float4*)(Lp + 4*i);
            const int k = k0 + 4*i;
            LATt[(k+0)*72 + r] = cf(v.x);
            LATt[(k+1)*72 + r] = cf(v.y);
            LATt[(k+2)*72 + r] = cf(v.z);
            LATt[(k+3)*72 + r] = cf(v.w);
        }
    }
    __syncthreads();

    // ---- QW = lat @ M_h; M_h rows reduced on-the-fly from g_pp ----
    {
        const int ts = t & 255, hsel = t >> 8;
        const int hh = hp * 2 + hsel;
        float* BufBase = BsAll + hsel * 2 * BSW;           // staging target
        const float* S0 = g_pp + (size_t)(0*8 + hh) * 16384;
        const float* S1 = g_pp + (size_t)(1*8 + hh) * 16384;
        const float* S2 = g_pp + (size_t)(2*8 + hh) * 16384;
        const float* S3 = g_pp + (size_t)(3*8 + hh) * 16384;
        const int br = ts >> 3, bc = (ts & 7) * 16;
        const size_t boff = (size_t)br * DIMM + bc;
        float4 pre[4];
        #pragma unroll
        for (int i = 0; i < 4; i++) pre[i] = sum4m(S0,S1,S2,S3, boff + 4*i, QSCALE);
        #pragma unroll
        for (int i = 0; i < 4; i++) {
            float4 v;
            v.x = cf(pre[i].x); v.y = cf(pre[i].y);
            v.z = cf(pre[i].z); v.w = cf(pre[i].w);
            *(float4*)&BufBase[br*136 + bc + 4*i] = v;
        }
        float qacc[8][4];
        #pragma unroll
        for (int j = 0; j < 8; j++)
            #pragma unroll
            for (int i = 0; i < 4; i++) qacc[j][i] = 0.f;
        const float* myBuf = BsAll + head * 2 * BSW;       // compute source
        for (int c = 0; c < 4; c++) {
            __syncthreads();
            if (c + 1 < 4) {
                const size_t off2 = boff + (size_t)(c + 1) * 32 * DIMM;
                #pragma unroll
                for (int i = 0; i < 4; i++) pre[i] = sum4m(S0,S1,S2,S3, off2 + 4*i, QSCALE);
            }
            frag_full(LATt, myBuf + (c & 1) * BSW, qacc, wm, wn, grp, qid, c * 32);
            if (c + 1 < 4) {
                float* dst = BufBase + ((c + 1) & 1) * BSW;
                #pragma unroll
                for (int i = 0; i < 4; i++) {
                    float4 v;
                    v.x = cf(pre[i].x); v.y = cf(pre[i].y);
                    v.z = cf(pre[i].z); v.w = cf(pre[i].w);
                    *(float4*)&dst[br*136 + bc + 4*i] = v;
                }
            }
        }
        #pragma unroll
        for (int j = 0; j < 8; j++) {
            const int c = wn + 8*j + 2*qid;
            QWt[(c  )*72 + wm+grp  ] = cf(qacc[j][0]);
            QWt[(c+1)*72 + wm+grp  ] = cf(qacc[j][1]);
            QWt[(c  )*72 + wm+grp+8] = cf(qacc[j][2]);
            QWt[(c+1)*72 + wm+grp+8] = cf(qacc[j][3]);
        }
    }
    // first S sync orders QWt stores before reads

    float O[8][4];
    #pragma unroll
    for (int j = 0; j < 8; j++)
        #pragma unroll
        for (int i = 0; i < 4; i++) O[j][i] = 0.f;

    // S-phase staging role: 64 kv rows x 32 dims per chunk
    const int sbn = t & 63, skd = (t >> 6) * 4;
    // PV staging role: 32 kv rows x 128 dims per chunk
    const int pbr = t >> 4, pbc = (t & 15) * 8;

    for (int kv0 = 0; kv0 < KVHALF; kv0 += 128) {
        const int valid = (KVHALF - kv0 < 128) ? (KVHALF - kv0) : 128;  // 128 or 32

        // ---- S = QW @ in^T in two kv halves of 64, shared B staging ----
        #pragma unroll
        for (int hn = 0; hn < 2; hn++) {
            const int validh = valid - hn * 64;
            if (validh > 0) {
                const int vh = validh < 64 ? validh : 64;
                const bool v = sbn < vh;
                const float* Bp = row_ptr(tensor, latents, bt,
                                          kvbase + kv0 + hn*64 + (v ? sbn : 0)) + skd;
                float4 pre = v ? *(const float4*)Bp : make_float4(0.f,0.f,0.f,0.f);
                {
                    float* dst = BsAll;
                    dst[(skd+0)*136 + sbn] = cf(pre.x);
                    dst[(skd+1)*136 + sbn] = cf(pre.y);
                    dst[(skd+2)*136 + sbn] = cf(pre.z);
                    dst[(skd+3)*136 + sbn] = cf(pre.w);
                }
                float sacc[4][4];
                #pragma unroll
                for (int j = 0; j < 4; j++)
                    #pragma unroll
                    for (int i = 0; i < 4; i++) sacc[j][i] = 0.f;
                for (int c = 0; c < 4; c++) {
                    __syncthreads();
                    if (c + 1 < 4)
                        pre = v ? *(const float4*)(Bp + (c+1)*32)
                                : make_float4(0.f,0.f,0.f,0.f);
                    frag_half(QWt, BsAll + (c & 1) * BSW, sacc, wm, wn2, grp, qid, c * 32);
                    if (c + 1 < 4) {
                        float* dst = BsAll + ((c + 1) & 1) * BSW;
                        dst[(skd+0)*136 + sbn] = cf(pre.x);
                        dst[(skd+1)*136 + sbn] = cf(pre.y);
                        dst[(skd+2)*136 + sbn] = cf(pre.z);
                        dst[(skd+3)*136 + sbn] = cf(pre.w);
                    }
                }
                #pragma unroll
                for (int j = 0; j < 4; j++) {
                    const int c = hn * 64 + wn2 + 8*j + 2*qid;
                    if (c < valid) {
                        SXt[(c  )*72 + wm+grp  ] = sacc[j][0];
                        SXt[(c  )*72 + wm+grp+8] = sacc[j][2];
                    }
                    if (c + 1 < valid) {
                        SXt[(c+1)*72 + wm+grp  ] = sacc[j][1];
                        SXt[(c+1)*72 + wm+grp+8] = sacc[j][3];
                    }
                }
            }
        }
        __syncthreads();

        // ---- online softmax: 2 heads x 64 rows x 4 parts = 512 threads ----
        {
            const int hs = t >> 8, row = (t >> 2) & 63, part = t & 3;
            float* SX = sm + 18432 + hs * 9216;
            float* mr = stats + hs * 64;
            float* lr = stats + 128 + hs * 64;
            float* rs = stats + 256 + hs * 64;
            const float mo = mr[row];
            float mx = mo;
            #pragma unroll 8
            for (int i = 0; i < 32; i++) {
                const int c = part + 4*i;
                if (c < valid) mx = fmaxf(mx, SX[c*72 + row]);
            }
            mx = fmaxf(mx, __shfl_xor_sync(0xffffffffu, mx, 1));
            mx = fmaxf(mx, __shfl_xor_sync(0xffffffffu, mx, 2));
            float s = 0.f;
            #pragma unroll 8
            for (int i = 0; i < 32; i++) {
                const int c = part + 4*i;
                if (c < valid) {
                    const float e = __expf(SX[c*72 + row] - mx);
                    SX[c*72 + row] = cf(e);
                    s += e;
                }
            }
            s += __shfl_xor_sync(0xffffffffu, s, 1);
            s += __shfl_xor_sync(0xffffffffu, s, 2);
            if (part == 0) {
                const float scale = __expf(mo - mx);
                lr[row] = lr[row] * scale + s;
                mr[row] = mx;
                rs[row] = scale;
            }
        }
        __syncthreads();

        // ---- rescale O, then O += P @ in (shared B staging, 32-kv chunks) ----
        {
            const float s0 = rsc[wm+grp], s1 = rsc[wm+grp+8];
            #pragma unroll
            for (int j = 0; j < 8; j++) {
                O[j][0] *= s0; O[j][1] *= s0;
                O[j][2] *= s1; O[j][3] *= s1;
            }
        }
        {
            const int nch = valid >> 5;                    // 4 or 1
            const float* Bp = row_ptr(tensor, latents, bt, kvbase + kv0 + pbr) + pbc;
            float4 p0 = *(const float4*)(Bp);
            float4 p1 = *(const float4*)(Bp + 4);
            {
                float* dst = BsAll + pbr * 136 + pbc;
                float4 w;
                w.x = cf(p0.x); w.y = cf(p0.y); w.z = cf(p0.z); w.w = cf(p0.w);
                *(float4*)dst = w;
                w.x = cf(p1.x); w.y = cf(p1.y); w.z = cf(p1.z); w.w = cf(p1.w);
                *(float4*)(dst + 4) = w;
            }
            for (int c = 0; c < nch; c++) {
                __syncthreads();
                if (c + 1 < nch) {
                    const float* Bp2 = row_ptr(tensor, latents, bt,
                                               kvbase + kv0 + (c+1)*32 + pbr) + pbc;
                    p0 = *(const float4*)(Bp2);
                    p1 = *(const float4*)(Bp2 + 4);
                }
                frag_full(SXt, BsAll + (c & 1) * BSW, O, wm, wn, grp, qid, c * 32);
                if (c + 1 < nch) {
                    float* dst = BsAll + ((c + 1) & 1) * BSW + pbr * 136 + pbc;
                    float4 w;
                    w.x = cf(p0.x); w.y = cf(p0.y); w.z = cf(p0.z); w.w = cf(p0.w);
                    *(float4*)dst = w;
                    w.x = cf(p1.x); w.y = cf(p1.y); w.z = cf(p1.z); w.w = cf(p1.w);
                    *(float4*)(dst + 4) = w;
                }
            }
        }
        __syncthreads();
    }

    // ---- epilogue: store (m,l) and un-normalized O ----
    if (t < 128) {
        const int hs = t >> 6, r = t & 63;
        const int zo = (bt * 8 + hp * 2 + hs) * 2 + half;
        g_ml2[(size_t)zo * NL + r] = make_float2(stats[hs*64 + r], stats[128 + hs*64 + r]);
    }
    float* P = g_po + (size_t)((bt * 8 + hglob) * 2 + half) * NL * DIMM;
    #pragma unroll
    for (int j = 0; j < 8; j++) {
        const int c = wn + 8*j + 2*qid;
        *(float2*)&P[(size_t)(wm+grp  ) * DIMM + c] = make_float2(O[j][0], O[j][1]);
        *(float2*)&P[(size_t)(wm+grp+8) * DIMM + c] = make_float2(O[j][2], O[j][3]);
    }
}

// ===========================================================================
// fp32 64x64 cores for split-K weight precompute (proven)
// ===========================================================================
__device__ __forceinline__ void f32_nn_core(
    const float* __restrict__ A, const float* __restrict__ B, float* __restrict__ C,
    int lda, int ldb, int ldc, int K, float alpha, int m0, int n0)
{
    __shared__ float As[16][68];
    __shared__ float Bsb[16][68];
    const int t  = threadIdx.x;
    const int tx = t & 15, ty = t >> 4;
    const int am = t >> 2, ak = (t & 3) << 2;
    const int bk = t >> 4, bn = (t & 15) << 2;
    const float* Ap = A + (size_t)(m0 + am) * lda + ak;
    const float* Bp = B + (size_t)bk * ldb + n0 + bn;
    float acc[4][4] = {};
    for (int kb = 0; kb < K; kb += 16) {
        float4 a = *(const float4*)(Ap + kb);
        float4 b = *(const float4*)(Bp + (size_t)kb * ldb);
        As[ak+0][am] = a.x; As[ak+1][am] = a.y; As[ak+2][am] = a.z; As[ak+3][am] = a.w;
        *(float4*)&Bsb[bk][bn] = b;
        __syncthreads();
        #pragma unroll
        for (int k = 0; k < 16; ++k) {
            float4 av = *(const float4*)&As[k][ty << 2];
            float4 bv = *(const float4*)&Bsb[k][tx << 2];
            acc[0][0] += av.x*bv.x; acc[0][1] += av.x*bv.y; acc[0][2] += av.x*bv.z; acc[0][3] += av.x*bv.w;
            acc[1][0] += av.y*bv.x; acc[1][1] += av.y*bv.y; acc[1][2] += av.y*bv.z; acc[1][3] += av.y*bv.w;
            acc[2][0] += av.z*bv.x; acc[2][1] += av.z*bv.y; acc[2][2] += av.z*bv.z; acc[2][3] += av.z*bv.w;
            acc[3][0] += av.w*bv.x; acc[3][1] += av.w*bv.y; acc[3][2] += av.w*bv.z; acc[3][3] += av.w*bv.w;
        }
        __syncthreads();
    }
    #pragma unroll
    for (int i = 0; i < 4; ++i) {
        float4 r;
        r.x = acc[i][0]*alpha; r.y = acc[i][1]*alpha; r.z = acc[i][2]*alpha; r.w = acc[i][3]*alpha;
        *(float4*)&C[(size_t)(m0 + (ty << 2) + i) * ldc + n0 + (tx << 2)] = r;
    }
}

__device__ __forceinline__ void f32_nt_core(
    const float* __restrict__ A, const float* __restrict__ Bm, float* __restrict__ C,
    int lda, int ldb, int ldc, int K, float alpha, int m0, int n0)
{
    __shared__ float As[16][68];
    __shared__ float Bsb[16][68];
    const int t  = threadIdx.x;
    const int tx = t & 15, ty = t >> 4;
    const int am = t >> 2, ak = (t & 3) << 2;
    const int bn = t >> 2, bq = (t & 3) << 2;
    const float* Ap = A  + (size_t)(m0 + am) * lda + ak;
    const float* Bp = Bm + (size_t)(n0 + bn) * ldb + bq;
    float acc[4][4] = {};
    for (int kb = 0; kb < K; kb += 16) {
        float4 a = *(const float4*)(Ap + kb);
        float4 b = *(const float4*)(Bp + kb);
        As[ak+0][am] = a.x; As[ak+1][am] = a.y; As[ak+2][am] = a.z; As[ak+3][am] = a.w;
        Bsb[bq+0][bn] = b.x; Bsb[bq+1][bn] = b.y; Bsb[bq+2][bn] = b.z; Bsb[bq+3][bn] = b.w;
        __syncthreads();
        #pragma unroll
        for (int k = 0; k < 16; ++k) {
            float4 av = *(const float4*)&As[k][ty << 2];
            float4 bv = *(const float4*)&Bsb[k][tx << 2];
            acc[0][0] += av.x*bv.x; acc[0][1] += av.x*bv.y; acc[0][2] += av.x*bv.z; acc[0][3] += av.x*bv.w;
            acc[1][0] += av.y*bv.x; acc[1][1] += av.y*bv.y; acc[1][2] += av.y*bv.z; acc[1][3] += av.y*bv.w;
            acc[2][0] += av.z*bv.x; acc[2][1] += av.z*bv.y; acc[2][2] += av.z*bv.z; acc[2][3] += av.z*bv.w;
            acc[3][0] += av.w*bv.x; acc[3][1] += av.w*bv.y; acc[3][2] += av.w*bv.z; acc[3][3] += av.w*bv.w;
        }
        __syncthreads();
    }
    #pragma unroll
    for (int i = 0; i < 4; ++i) {
        float4 r;
        r.x = acc[i][0]*alpha; r.y = acc[i][1]*alpha; r.z = acc[i][2]*alpha; r.w = acc[i][3]*alpha;
        *(float4*)&C[(size_t)(m0 + (ty << 2) + i) * ldc + n0 + (tx << 2)] = r;
    }
}

// k_prep_part: blocks 0..255 = split-K weight partials; 256..287 zero `out`
__global__ void k_prep_part(const float* __restrict__ Wq, const float* __restrict__ Wkv,
                            const float* __restrict__ Wo, float* __restrict__ out)
{
    const int b = blockIdx.x;
    if (b >= 256) {
        const int i = (b - 256) * 256 + threadIdx.x;
        float4* o4 = (float4*)out;
        #pragma unroll
        for (int j = 0; j < 4; j++)
            o4[i * 4 + j] = make_float4(0.f, 0.f, 0.f, 0.f);
        return;
    }
    const int isN = b >> 7, idx = b & 127;
    const int h = idx >> 4, sub = (idx >> 2) & 3, ks = idx & 3;
    const int m0 = (sub >> 1) * 64, n0 = (sub & 1) * 64, k0 = ks * 64;
    float* C = g_pp + ((size_t)(isN * 4 + ks) * 8 + h) * (DIMM * DIMM);
    if (!isN)
        f32_nt_core(Wq + h * 256 + k0, Wkv + h * 256 + k0, C,
                    INNER, 2 * INNER, DIMM, 64, 1.0f, m0, n0);
    else
        f32_nn_core(Wkv + INNER + h * 256 + k0, Wo + ((size_t)h * 256 + k0) * DIMM, C,
                    2 * INNER, DIMM, DIMM, 64, 1.0f, m0, n0);
}

// ===========================================================================
// k_final_part: grid (16, 16) = (h*2 + ksplit, bt). Each CTA computes the
// K=64 dim-slice [ks2*64, ks2*64+64) of partial_h = PI_h @ N_h, with the
// flash-combine fused into the A loader and the N_h slice reduced on the fly
// from g_pp. 256 threads; accumulates into out via atomicAdd.
// ===========================================================================
__global__ void __launch_bounds__(256) k_final_part(float* __restrict__ out)
{
    __shared__ float As[32][72];
    __shared__ float Bsb[32][136];
    const int hx = blockIdx.x, bt = blockIdx.y;
    const int h = hx >> 1, ks2 = hx & 1;
    const int k0 = ks2 * 64;
    const int z = bt * HEADS + h;
    float* C = out + (size_t)bt * NL * DIMM;

    const int t    = threadIdx.x;
    const int warp = t >> 5, lane = t & 31;
    const int grp  = lane >> 2, qid = lane & 3;
    const int wm   = (warp & 3) * 16, wn = (warp >> 2) * 64;

    const int arow = t >> 2, ak0 = (t & 3) * 8;

    float2 ml0 = g_ml2[(size_t)(z*2  ) * NL + arow];
    float2 ml1 = g_ml2[(size_t)(z*2+1) * NL + arow];
    const float mm = fmaxf(ml0.x, ml1.x);
    const float a0 = __expf(ml0.x - mm), a1 = __expf(ml1.x - mm);
    const float il = 1.0f / (ml0.y * a0 + ml1.y * a1);
    const float e0 = a0 * il, e1 = a1 * il;

    const float* O0 = g_po + (size_t)(z*2  ) * NL * DIMM + (size_t)arow * DIMM + k0 + ak0;
    const float* O1 = g_po + (size_t)(z*2+1) * NL * DIMM + (size_t)arow * DIMM + k0 + ak0;

    // N_h slice bases (isN=1): slice ks -> g_pp + ((4+ks)*8 + h) * 16384
    const float* N0 = g_pp + (size_t)(32 + 0*8 + h) * 16384;
    const float* N1 = g_pp + (size_t)(32 + 1*8 + h) * 16384;
    const float* N2 = g_pp + (size_t)(32 + 2*8 + h) * 16384;
    const float* N3 = g_pp + (size_t)(32 + 3*8 + h) * 16384;
    const int brow = t >> 3, bcol = (t & 7) * 16;
    const size_t boff = (size_t)(k0 + brow) * DIMM + bcol;

    float acc[8][4];
    #pragma unroll
    for (int j = 0; j < 8; j++)
        #pragma unroll
        for (int i = 0; i < 4; i++) acc[j][i] = 0.f;

    float4 o0[2], o1[2], br[4];
    #pragma unroll
    for (int i = 0; i < 2; i++) {
        o0[i] = *(const float4*)(O0 + 4*i);
        o1[i] = *(const float4*)(O1 + 4*i);
    }
    #pragma unroll
    for (int i = 0; i < 4; i++) br[i] = sum4m(N0,N1,N2,N3, boff + 4*i, 1.0f);

    const int nk = 2;   // K = 64 per CTA
    for (int c = 0; c < nk; c++) {
        #pragma unroll
        for (int i = 0; i < 2; i++) {
            const int kc = ak0 + 4*i;
            As[kc+0][arow] = cf(e0*o0[i].x + e1*o1[i].x);
            As[kc+1][arow] = cf(e0*o0[i].y + e1*o1[i].y);
            As[kc+2][arow] = cf(e0*o0[i].z + e1*o1[i].z);
            As[kc+3][arow] = cf(e0*o0[i].w + e1*o1[i].w);
        }
        #pragma unroll
        for (int i = 0; i < 4; i++) {
            float4 v;
            v.x = cf(br[i].x); v.y = cf(br[i].y);
            v.z = cf(br[i].z); v.w = cf(br[i].w);
            *(float4*)&Bsb[brow][bcol + 4*i] = v;
        }
        __syncthreads();
        if (c + 1 < nk) {
            #pragma unroll
            for (int i = 0; i < 2; i++) {
                o0[i] = *(const float4*)(O0 + (c+1)*32 + 4*i);
                o1[i] = *(const float4*)(O1 + (c+1)*32 + 4*i);
            }
            const size_t off2 = boff + (size_t)(c + 1) * 32 * DIMM;
            #pragma unroll
            for (int i = 0; i < 4; i++) br[i] = sum4m(N0,N1,N2,N3, off2 + 4*i, 1.0f);
        }
        #pragma unroll
        for (int kk = 0; kk < 32; kk += 8) {
            unsigned a[4], b[8][2];
            a[0] = uu(As[kk+qid  ][wm+grp  ]);
            a[1] = uu(As[kk+qid  ][wm+grp+8]);
            a[2] = uu(As[kk+qid+4][wm+grp  ]);
            a[3] = uu(As[kk+qid+4][wm+grp+8]);
            #pragma unroll
            for (int j = 0; j < 8; j++) {
                b[j][0] = uu(Bsb[kk+qid  ][wn+8*j+grp]);
                b[j][1] = uu(Bsb[kk+qid+4][wn+8*j+grp]);
            }
            #pragma unroll
            for (int j = 0; j < 8; j++) mma8(acc[j], a, b[j]);
        }
        __syncthreads();
    }
    #pragma unroll
    for (int j = 0; j < 8; j++) {
        const int col = wn + 8*j + 2*qid;
        atomicAdd(&C[(size_t)(wm+grp  ) * DIMM + col    ], acc[j][0]);
        atomicAdd(&C[(size_t)(wm+grp  ) * DIMM + col + 1], acc[j][1]);
        atomicAdd(&C[(size_t)(wm+grp+8) * DIMM + col    ], acc[j][2]);
        atomicAdd(&C[(size_t)(wm+grp+8) * DIMM + col + 1], acc[j][3]);
    }
}

// ---------------------------------------------------------------------------

extern "C" void kernel_launch(void* const* d_in, const int* in_sizes, int n_in,
                              void* d_out, int out_size)
{
    const float* tensor  = (const float*)d_in[0];
    const float* latents = (const float*)d_in[1];
    const float* Wq      = (const float*)d_in[2];
    const float* Wkv     = (const float*)d_in[3];
    const float* Wo      = (const float*)d_in[4];
    float*       out     = (float*)d_out;

    (void)in_sizes; (void)n_in; (void)out_size;

    cudaFuncSetAttribute(k_flash, cudaFuncAttributeMaxDynamicSharedMemorySize, FLASH_SMEM);

    k_prep_part <<<288, 256>>>(Wq, Wkv, Wo, out);
    k_flash     <<<BTT * HEADS, 512, FLASH_SMEM>>>(tensor, latents);
    k_final_part<<<dim3(2 * HEADS, BTT), 256>>>(out);
}

// round 15
// speedup vs baseline: 1.1493x; 1.1493x over previous
#include <cuda_runtime.h>
#include <math.h>

// Problem constants
#define BTT     16
#define NM      1024
#define NL      64
#define NKV     1088
#define DIMM    128
#define HEADS   8
#define INNER   2048
#define QSCALE  0.08838834764831845f   // 128^-0.5
#define KVHALF  544

// Static device scratch
static __device__ float  g_pp[2 * 4 * 8 * DIMM * DIMM];       // split-K prep partials
static __device__ float  g_m [HEADS * DIMM * DIMM];           // M_h = scale*Wq_h@Wk_h^T
static __device__ float  g_n [HEADS * DIMM * DIMM];           // N_h = Wv_h@Wo_h
static __device__ float  g_po[2 * BTT * HEADS * NL * DIMM];   // un-normalized O halves
static __device__ float2 g_ml2[2 * BTT * HEADS * NL];         // (m, l) per half per row

// fp32 -> tf32 round-to-nearest
__device__ __forceinline__ float cf(float x){
    unsigned u; asm("cvt.rna.tf32.f32 %0, %1;" : "=r"(u) : "f"(x));
    return __uint_as_float(u);
}
__device__ __forceinline__ unsigned uu(float x){ return __float_as_uint(x); }

__device__ __forceinline__ void mma8(float* d, const unsigned* a, const unsigned* b){
    asm volatile("mma.sync.aligned.m16n8k8.row.col.f32.tf32.tf32.f32 "
        "{%0,%1,%2,%3}, {%4,%5,%6,%7}, {%8,%9}, {%0,%1,%2,%3};"
        : "+f"(d[0]), "+f"(d[1]), "+f"(d[2]), "+f"(d[3])
        : "r"(a[0]), "r"(a[1]), "r"(a[2]), "r"(a[3]), "r"(b[0]), "r"(b[1]));
}

// row r of concat(tensor[bt], latents[bt])
__device__ __forceinline__ const float* row_ptr(
    const float* __restrict__ tensor, const float* __restrict__ latents, int bt, int r)
{
    return (r < NM) ? tensor  + ((size_t)bt * NM + r)        * DIMM
                    : latents + ((size_t)bt * NL + (r - NM)) * DIMM;
}

#define BSW 4352   // words per B staging buffer (32*136)

// full-width fragment step: warp tile 16x64
__device__ __forceinline__ void frag_full(
    const float* __restrict__ At, const float* __restrict__ Bs,
    float acc[8][4], int wm, int wn, int grp, int qid, int akbase)
{
    #pragma unroll
    for (int kk = 0; kk < 32; kk += 8) {
        unsigned a[4], b[8][2];
        const int k0 = akbase + kk;
        a[0] = uu(At[(k0+qid  )*72 + wm+grp  ]);
        a[1] = uu(At[(k0+qid  )*72 + wm+grp+8]);
        a[2] = uu(At[(k0+qid+4)*72 + wm+grp  ]);
        a[3] = uu(At[(k0+qid+4)*72 + wm+grp+8]);
        #pragma unroll
        for (int j = 0; j < 8; j++) {
            b[j][0] = uu(Bs[(kk+qid  )*136 + wn+8*j+grp]);
            b[j][1] = uu(Bs[(kk+qid+4)*136 + wn+8*j+grp]);
        }
        #pragma unroll
        for (int j = 0; j < 8; j++) mma8(acc[j], a, b[j]);
    }
}

// half-width fragment step: warp tile 16x32 (S phase)
__device__ __forceinline__ void frag_half(
    const float* __restrict__ At, const float* __restrict__ Bs,
    float acc[4][4], int wm, int wn2, int grp, int qid, int akbase)
{
    #pragma unroll
    for (int kk = 0; kk < 32; kk += 8) {
        unsigned a[4], b[4][2];
        const int k0 = akbase + kk;
        a[0] = uu(At[(k0+qid  )*72 + wm+grp  ]);
        a[1] = uu(At[(k0+qid  )*72 + wm+grp+8]);
        a[2] = uu(At[(k0+qid+4)*72 + wm+grp  ]);
        a[3] = uu(At[(k0+qid+4)*72 + wm+grp+8]);
        #pragma unroll
        for (int j = 0; j < 4; j++) {
            b[j][0] = uu(Bs[(kk+qid  )*136 + wn2+8*j+grp]);
            b[j][1] = uu(Bs[(kk+qid+4)*136 + wn2+8*j+grp]);
        }
        #pragma unroll
        for (int j = 0; j < 4; j++) mma8(acc[j], a, b[j]);
    }
}

// ===========================================================================
// k_flash (R13 champion, verbatim): grid 128 = (bt, head-pair, kv-half),
// 512 threads. Warps 0-7 = head A, 8-15 = head B; KV staged ONCE per pair.
// ===========================================================================
#define FLASH_WORDS (2*9216 + 2*9216 + 4*BSW + 384)
#define FLASH_SMEM  (FLASH_WORDS * 4)   // 218624 bytes

__global__ void __launch_bounds__(512, 1) k_flash(
    const float* __restrict__ tensor, const float* __restrict__ latents)
{
    extern __shared__ float sm[];
    const int zz = blockIdx.x;                 // 0..127
    const int half = zz & 1, hp = (zz >> 1) & 3, bt = zz >> 3;
    const int kvbase = half * KVHALF;

    const int t = threadIdx.x, warp = t >> 5, lane = t & 31;
    const int head = warp >> 3, w8 = warp & 7;
    const int grp = lane >> 2, qid = lane & 3;
    const int wm  = (w8 & 3) * 16;
    const int wn  = (w8 >> 2) * 64;
    const int wn2 = (w8 >> 2) * 32;
    const int hglob = hp * 2 + head;

    float* QWt   = sm + head * 9216;           // [128 dims][72]
    float* LATt  = sm + 18432;                 // latents transposed (shared)
    float* SXt   = sm + 18432 + head * 9216;   // scores/P [kv][72] per head
    float* BsAll = sm + 36864;                 // 4 x [32][136]
    float* stats = sm + 36864 + 4*BSW;         // m[128] | l[128] | rsc[128]
    float* rsc   = stats + 256 + head * 64;

    if (t < 128) { stats[t] = -INFINITY; stats[128 + t] = 0.f; }

    // stage latents[bt] (64x128) transposed -> LATt (shared by both heads)
    {
        const int r = t >> 3, k0 = (t & 7) * 16;
        const float* Lp = latents + (size_t)bt * NL * DIMM + (size_t)r * DIMM + k0;
        #pragma unroll
        for (int i = 0; i < 4; i++) {
            float4 v = *(const float4*)(Lp + 4*i);
            const int k = k0 + 4*i;
            LATt[(k+0)*72 + r] = cf(v.x);
            LATt[(k+1)*72 + r] = cf(v.y);
            LATt[(k+2)*72 + r] = cf(v.z);
            LATt[(k+3)*72 + r] = cf(v.w);
        }
    }
    __syncthreads();

    // ---- QW = lat @ M_h, each head double-buffered in its own buffer pair ----
    {
        const int ts = t & 255, hsel = t >> 8;
        float* BufBase = BsAll + hsel * 2 * BSW;           // staging target
        const float* Bg = g_m + (size_t)(hp * 2 + hsel) * DIMM * DIMM;
        const int br = ts >> 3, bc = (ts & 7) * 16;
        const float* Bp = Bg + (size_t)br * DIMM + bc;
        float4 pre[4];
        #pragma unroll
        for (int i = 0; i < 4; i++) pre[i] = *(const float4*)(Bp + 4*i);
        #pragma unroll
        for (int i = 0; i < 4; i++) {
            float4 v;
            v.x = cf(pre[i].x); v.y = cf(pre[i].y);
            v.z = cf(pre[i].z); v.w = cf(pre[i].w);
            *(float4*)&BufBase[br*136 + bc + 4*i] = v;
        }
        float qacc[8][4];
        #pragma unroll
        for (int j = 0; j < 8; j++)
            #pragma unroll
            for (int i = 0; i < 4; i++) qacc[j][i] = 0.f;
        const float* myBuf = BsAll + head * 2 * BSW;       // compute source
        for (int c = 0; c < 4; c++) {
            __syncthreads();
            if (c + 1 < 4) {
                const float* Bp2 = Bp + (size_t)(c + 1) * 32 * DIMM;
                #pragma unroll
                for (int i = 0; i < 4; i++) pre[i] = *(const float4*)(Bp2 + 4*i);
            }
            frag_full(LATt, myBuf + (c & 1) * BSW, qacc, wm, wn, grp, qid, c * 32);
            if (c + 1 < 4) {
                float* dst = BufBase + ((c + 1) & 1) * BSW;
                #pragma unroll
                for (int i = 0; i < 4; i++) {
                    float4 v;
                    v.x = cf(pre[i].x); v.y = cf(pre[i].y);
                    v.z = cf(pre[i].z); v.w = cf(pre[i].w);
                    *(float4*)&dst[br*136 + bc + 4*i] = v;
                }
            }
        }
        #pragma unroll
        for (int j = 0; j < 8; j++) {
            const int c = wn + 8*j + 2*qid;
            QWt[(c  )*72 + wm+grp  ] = cf(qacc[j][0]);
            QWt[(c+1)*72 + wm+grp  ] = cf(qacc[j][1]);
            QWt[(c  )*72 + wm+grp+8] = cf(qacc[j][2]);
            QWt[(c+1)*72 + wm+grp+8] = cf(qacc[j][3]);
        }
    }
    // first S sync orders QWt stores before reads

    float O[8][4];
    #pragma unroll
    for (int j = 0; j < 8; j++)
        #pragma unroll
        for (int i = 0; i < 4; i++) O[j][i] = 0.f;

    // S-phase staging role: 64 kv rows x 32 dims per chunk
    const int sbn = t & 63, skd = (t >> 6) * 4;
    // PV staging role: 32 kv rows x 128 dims per chunk
    const int pbr = t >> 4, pbc = (t & 15) * 8;

    for (int kv0 = 0; kv0 < KVHALF; kv0 += 128) {
        const int valid = (KVHALF - kv0 < 128) ? (KVHALF - kv0) : 128;  // 128 or 32

        // ---- S = QW @ in^T in two kv halves of 64, shared B staging ----
        #pragma unroll
        for (int hn = 0; hn < 2; hn++) {
            const int validh = valid - hn * 64;
            if (validh > 0) {
                const int vh = validh < 64 ? validh : 64;
                const bool v = sbn < vh;
                const float* Bp = row_ptr(tensor, latents, bt,
                                          kvbase + kv0 + hn*64 + (v ? sbn : 0)) + skd;
                float4 pre = v ? *(const float4*)Bp : make_float4(0.f,0.f,0.f,0.f);
                {
                    float* dst = BsAll;
                    dst[(skd+0)*136 + sbn] = cf(pre.x);
                    dst[(skd+1)*136 + sbn] = cf(pre.y);
                    dst[(skd+2)*136 + sbn] = cf(pre.z);
                    dst[(skd+3)*136 + sbn] = cf(pre.w);
                }
                float sacc[4][4];
                #pragma unroll
                for (int j = 0; j < 4; j++)
                    #pragma unroll
                    for (int i = 0; i < 4; i++) sacc[j][i] = 0.f;
                for (int c = 0; c < 4; c++) {
                    __syncthreads();
                    if (c + 1 < 4)
                        pre = v ? *(const float4*)(Bp + (c+1)*32)
                                : make_float4(0.f,0.f,0.f,0.f);
                    frag_half(QWt, BsAll + (c & 1) * BSW, sacc, wm, wn2, grp, qid, c * 32);
                    if (c + 1 < 4) {
                        float* dst = BsAll + ((c + 1) & 1) * BSW;
                        dst[(skd+0)*136 + sbn] = cf(pre.x);
                        dst[(skd+1)*136 + sbn] = cf(pre.y);
                        dst[(skd+2)*136 + sbn] = cf(pre.z);
                        dst[(skd+3)*136 + sbn] = cf(pre.w);
                    }
                }
                #pragma unroll
                for (int j = 0; j < 4; j++) {
                    const int c = hn * 64 + wn2 + 8*j + 2*qid;
                    if (c < valid) {
                        SXt[(c  )*72 + wm+grp  ] = sacc[j][0];
                        SXt[(c  )*72 + wm+grp+8] = sacc[j][2];
                    }
                    if (c + 1 < valid) {
                        SXt[(c+1)*72 + wm+grp  ] = sacc[j][1];
                        SXt[(c+1)*72 + wm+grp+8] = sacc[j][3];
                    }
                }
            }
        }
        __syncthreads();

        // ---- online softmax: 2 heads x 64 rows x 4 parts = 512 threads ----
        {
            const int hs = t >> 8, row = (t >> 2) & 63, part = t & 3;
            float* SX = sm + 18432 + hs * 9216;
            float* mr = stats + hs * 64;
            float* lr = stats + 128 + hs * 64;
            float* rs = stats + 256 + hs * 64;
            const float mo = mr[row];
            float mx = mo;
            #pragma unroll 8
            for (int i = 0; i < 32; i++) {
                const int c = part + 4*i;
                if (c < valid) mx = fmaxf(mx, SX[c*72 + row]);
            }
            mx = fmaxf(mx, __shfl_xor_sync(0xffffffffu, mx, 1));
            mx = fmaxf(mx, __shfl_xor_sync(0xffffffffu, mx, 2));
            float s = 0.f;
            #pragma unroll 8
            for (int i = 0; i < 32; i++) {
                const int c = part + 4*i;
                if (c < valid) {
                    const float e = __expf(SX[c*72 + row] - mx);
                    SX[c*72 + row] = cf(e);
                    s += e;
                }
            }
            s += __shfl_xor_sync(0xffffffffu, s, 1);
            s += __shfl_xor_sync(0xffffffffu, s, 2);
            if (part == 0) {
                const float scale = __expf(mo - mx);
                lr[row] = lr[row] * scale + s;
                mr[row] = mx;
                rs[row] = scale;
            }
        }
        __syncthreads();

        // ---- rescale O, then O += P @ in (shared B staging, 32-kv chunks) ----
        {
            const float s0 = rsc[wm+grp], s1 = rsc[wm+grp+8];
            #pragma unroll
            for (int j = 0; j < 8; j++) {
                O[j][0] *= s0; O[j][1] *= s0;
                O[j][2] *= s1; O[j][3] *= s1;
            }
        }
        {
            const int nch = valid >> 5;                    // 4 or 1
            const float* Bp = row_ptr(tensor, latents, bt, kvbase + kv0 + pbr) + pbc;
            float4 p0 = *(const float4*)(Bp);
            float4 p1 = *(const float4*)(Bp + 4);
            {
                float* dst = BsAll + pbr * 136 + pbc;
                float4 w;
                w.x = cf(p0.x); w.y = cf(p0.y); w.z = cf(p0.z); w.w = cf(p0.w);
                *(float4*)dst = w;
                w.x = cf(p1.x); w.y = cf(p1.y); w.z = cf(p1.z); w.w = cf(p1.w);
                *(float4*)(dst + 4) = w;
            }
            for (int c = 0; c < nch; c++) {
                __syncthreads();
                if (c + 1 < nch) {
                    const float* Bp2 = row_ptr(tensor, latents, bt,
                                               kvbase + kv0 + (c+1)*32 + pbr) + pbc;
                    p0 = *(const float4*)(Bp2);
                    p1 = *(const float4*)(Bp2 + 4);
                }
                frag_full(SXt, BsAll + (c & 1) * BSW, O, wm, wn, grp, qid, c * 32);
                if (c + 1 < nch) {
                    float* dst = BsAll + ((c + 1) & 1) * BSW + pbr * 136 + pbc;
                    float4 w;
                    w.x = cf(p0.x); w.y = cf(p0.y); w.z = cf(p0.z); w.w = cf(p0.w);
                    *(float4*)dst = w;
                    w.x = cf(p1.x); w.y = cf(p1.y); w.z = cf(p1.z); w.w = cf(p1.w);
                    *(float4*)(dst + 4) = w;
                }
            }
        }
        __syncthreads();
    }

    // ---- epilogue: store (m,l) and un-normalized O ----
    if (t < 128) {
        const int hs = t >> 6, r = t & 63;
        const int zo = (bt * 8 + hp * 2 + hs) * 2 + half;
        g_ml2[(size_t)zo * NL + r] = make_float2(stats[hs*64 + r], stats[128 + hs*64 + r]);
    }
    float* P = g_po + (size_t)((bt * 8 + hglob) * 2 + half) * NL * DIMM;
    #pragma unroll
    for (int j = 0; j < 8; j++) {
        const int c = wn + 8*j + 2*qid;
        *(float2*)&P[(size_t)(wm+grp  ) * DIMM + c] = make_float2(O[j][0], O[j][1]);
        *(float2*)&P[(size_t)(wm+grp+8) * DIMM + c] = make_float2(O[j][2], O[j][3]);
    }
}

// ===========================================================================
// fp32 64x64 cores for split-K weight precompute (proven)
// ===========================================================================
__device__ __forceinline__ void f32_nn_core(
    const float* __restrict__ A, const float* __restrict__ B, float* __restrict__ C,
    int lda, int ldb, int ldc, int K, float alpha, int m0, int n0)
{
    __shared__ float As[16][68];
    __shared__ float Bsb[16][68];
    const int t  = threadIdx.x;
    const int tx = t & 15, ty = t >> 4;
    const int am = t >> 2, ak = (t & 3) << 2;
    const int bk = t >> 4, bn = (t & 15) << 2;
    const float* Ap = A + (size_t)(m0 + am) * lda + ak;
    const float* Bp = B + (size_t)bk * ldb + n0 + bn;
    float acc[4][4] = {};
    for (int kb = 0; kb < K; kb += 16) {
        float4 a = *(const float4*)(Ap + kb);
        float4 b = *(const float4*)(Bp + (size_t)kb * ldb);
        As[ak+0][am] = a.x; As[ak+1][am] = a.y; As[ak+2][am] = a.z; As[ak+3][am] = a.w;
        *(float4*)&Bsb[bk][bn] = b;
        __syncthreads();
        #pragma unroll
        for (int k = 0; k < 16; ++k) {
            float4 av = *(const float4*)&As[k][ty << 2];
            float4 bv = *(const float4*)&Bsb[k][tx << 2];
            acc[0][0] += av.x*bv.x; acc[0][1] += av.x*bv.y; acc[0][2] += av.x*bv.z; acc[0][3] += av.x*bv.w;
            acc[1][0] += av.y*bv.x; acc[1][1] += av.y*bv.y; acc[1][2] += av.y*bv.z; acc[1][3] += av.y*bv.w;
            acc[2][0] += av.z*bv.x; acc[2][1] += av.z*bv.y; acc[2][2] += av.z*bv.z; acc[2][3] += av.z*bv.w;
            acc[3][0] += av.w*bv.x; acc[3][1] += av.w*bv.y; acc[3][2] += av.w*bv.z; acc[3][3] += av.w*bv.w;
        }
        __syncthreads();
    }
    #pragma unroll
    for (int i = 0; i < 4; ++i) {
        float4 r;
        r.x = acc[i][0]*alpha; r.y = acc[i][1]*alpha; r.z = acc[i][2]*alpha; r.w = acc[i][3]*alpha;
        *(float4*)&C[(size_t)(m0 + (ty << 2) + i) * ldc + n0 + (tx << 2)] = r;
    }
}

__device__ __forceinline__ void f32_nt_core(
    const float* __restrict__ A, const float* __restrict__ Bm, float* __restrict__ C,
    int lda, int ldb, int ldc, int K, float alpha, int m0, int n0)
{
    __shared__ float As[16][68];
    __shared__ float Bsb[16][68];
    const int t  = threadIdx.x;
    const int tx = t & 15, ty = t >> 4;
    const int am = t >> 2, ak = (t & 3) << 2;
    const int bn = t >> 2, bq = (t & 3) << 2;
    const float* Ap = A  + (size_t)(m0 + am) * lda + ak;
    const float* Bp = Bm + (size_t)(n0 + bn) * ldb + bq;
    float acc[4][4] = {};
    for (int kb = 0; kb < K; kb += 16) {
        float4 a = *(const float4*)(Ap + kb);
        float4 b = *(const float4*)(Bp + kb);
        As[ak+0][am] = a.x; As[ak+1][am] = a.y; As[ak+2][am] = a.z; As[ak+3][am] = a.w;
        Bsb[bq+0][bn] = b.x; Bsb[bq+1][bn] = b.y; Bsb[bq+2][bn] = b.z; Bsb[bq+3][bn] = b.w;
        __syncthreads();
        #pragma unroll
        for (int k = 0; k < 16; ++k) {
            float4 av = *(const float4*)&As[k][ty << 2];
            float4 bv = *(const float4*)&Bsb[k][tx << 2];
            acc[0][0] += av.x*bv.x; acc[0][1] += av.x*bv.y; acc[0][2] += av.x*bv.z; acc[0][3] += av.x*bv.w;
            acc[1][0] += av.y*bv.x; acc[1][1] += av.y*bv.y; acc[1][2] += av.y*bv.z; acc[1][3] += av.y*bv.w;
            acc[2][0] += av.z*bv.x; acc[2][1] += av.z*bv.y; acc[2][2] += av.z*bv.z; acc[2][3] += av.z*bv.w;
            acc[3][0] += av.w*bv.x; acc[3][1] += av.w*bv.y; acc[3][2] += av.w*bv.z; acc[3][3] += av.w*bv.w;
        }
        __syncthreads();
    }
    #pragma unroll
    for (int i = 0; i < 4; ++i) {
        float4 r;
        r.x = acc[i][0]*alpha; r.y = acc[i][1]*alpha; r.z = acc[i][2]*alpha; r.w = acc[i][3]*alpha;
        *(float4*)&C[(size_t)(m0 + (ty << 2) + i) * ldc + n0 + (tx << 2)] = r;
    }
}

// k_prep_part: blocks 0..255 = split-K weight partials; 256..287 zero `out`
__global__ void k_prep_part(const float* __restrict__ Wq, const float* __restrict__ Wkv,
                            const float* __restrict__ Wo, float* __restrict__ out)
{
    const int b = blockIdx.x;
    if (b >= 256) {
        const int i = (b - 256) * 256 + threadIdx.x;
        float4* o4 = (float4*)out;
        #pragma unroll
        for (int j = 0; j < 4; j++)
            o4[i * 4 + j] = make_float4(0.f, 0.f, 0.f, 0.f);
        return;
    }
    const int isN = b >> 7, idx = b & 127;
    const int h = idx >> 4, sub = (idx >> 2) & 3, ks = idx & 3;
    const int m0 = (sub >> 1) * 64, n0 = (sub & 1) * 64, k0 = ks * 64;
    float* C = g_pp + ((size_t)(isN * 4 + ks) * 8 + h) * (DIMM * DIMM);
    if (!isN)
        f32_nt_core(Wq + h * 256 + k0, Wkv + h * 256 + k0, C,
                    INNER, 2 * INNER, DIMM, 64, 1.0f, m0, n0);
    else
        f32_nn_core(Wkv + INNER + h * 256 + k0, Wo + ((size_t)h * 256 + k0) * DIMM, C,
                    2 * INNER, DIMM, DIMM, 64, 1.0f, m0, n0);
}

// k_prep_red: sum the 4 K-slices -> g_m (x QSCALE) / g_n
__global__ void k_prep_red()
{
    const int i = blockIdx.x * 256 + threadIdx.x;   // float4 idx, 65536 total
    const int isN = i >> 15, j = i & 32767;
    const int h = j >> 12, e = j & 4095;
    const float4* pp = (const float4*)g_pp;
    float4 r = make_float4(0.f, 0.f, 0.f, 0.f);
    #pragma unroll
    for (int ks = 0; ks < 4; ks++) {
        float4 a = pp[((size_t)(isN * 4 + ks) * 8 + h) * 4096 + e];
        r.x += a.x; r.y += a.y; r.z += a.z; r.w += a.w;
    }
    if (!isN) {
        r.x *= QSCALE; r.y *= QSCALE; r.z *= QSCALE; r.w *= QSCALE;
        ((float4*)g_m)[(size_t)h * 4096 + e] = r;
    } else {
        ((float4*)g_n)[(size_t)h * 4096 + e] = r;
    }
}

// ===========================================================================
// k_final_part: grid (16, 16) = (h*2 + ks2, bt). Each CTA computes the K=64
// dim-slice [ks2*64, +64) of partial_h = PI_h @ N_h (B from reduced g_n),
// combine fused into the A loader, 256 threads, atomicAdd into out.
// ===========================================================================
__global__ void __launch_bounds__(256) k_final_part(float* __restrict__ out)
{
    __shared__ float As[32][72];
    __shared__ float Bsb[32][136];
    const int hx = blockIdx.x, bt = blockIdx.y;
    const int h = hx >> 1, ks2 = hx & 1;
    const int k0 = ks2 * 64;
    const int z = bt * HEADS + h;
    const float* B = g_n + (size_t)h * DIMM * DIMM;
    float*       C = out + (size_t)bt * NL * DIMM;

    const int t    = threadIdx.x;
    const int warp = t >> 5, lane = t & 31;
    const int grp  = lane >> 2, qid = lane & 3;
    const int wm   = (warp & 3) * 16, wn = (warp >> 2) * 64;

    const int arow = t >> 2, ak0 = (t & 3) * 8;

    float2 ml0 = g_ml2[(size_t)(z*2  ) * NL + arow];
    float2 ml1 = g_ml2[(size_t)(z*2+1) * NL + arow];
    const float mm = fmaxf(ml0.x, ml1.x);
    const float a0 = __expf(ml0.x - mm), a1 = __expf(ml1.x - mm);
    const float il = 1.0f / (ml0.y * a0 + ml1.y * a1);
    const float e0 = a0 * il, e1 = a1 * il;

    const float* O0 = g_po + (size_t)(z*2  ) * NL * DIMM + (size_t)arow * DIMM + k0 + ak0;
    const float* O1 = g_po + (size_t)(z*2+1) * NL * DIMM + (size_t)arow * DIMM + k0 + ak0;
    const int brow = t >> 3, bcol = (t & 7) * 16;
    const float* Bp = B + (size_t)(k0 + brow) * DIMM + bcol;

    float acc[8][4];
    #pragma unroll
    for (int j = 0; j < 8; j++)
        #pragma unroll
        for (int i = 0; i < 4; i++) acc[j][i] = 0.f;

    float4 o0[2], o1[2], br[4];
    #pragma unroll
    for (int i = 0; i < 2; i++) {
        o0[i] = *(const float4*)(O0 + 4*i);
        o1[i] = *(const float4*)(O1 + 4*i);
    }
    #pragma unroll
    for (int i = 0; i < 4; i++) br[i] = *(const float4*)(Bp + 4*i);

    const int nk = 2;   // K = 64 per CTA
    for (int c = 0; c < nk; c++) {
        #pragma unroll
        for (int i = 0; i < 2; i++) {
            const int kc = ak0 + 4*i;
            As[kc+0][arow] = cf(e0*o0[i].x + e1*o1[i].x);
            As[kc+1][arow] = cf(e0*o0[i].y + e1*o1[i].y);
            As[kc+2][arow] = cf(e0*o0[i].z + e1*o1[i].z);
            As[kc+3][arow] = cf(e0*o0[i].w + e1*o1[i].w);
        }
        #pragma unroll
        for (int i = 0; i < 4; i++) {
            float4 v;
            v.x = cf(br[i].x); v.y = cf(br[i].y);
            v.z = cf(br[i].z); v.w = cf(br[i].w);
            *(float4*)&Bsb[brow][bcol + 4*i] = v;
        }
        __syncthreads();
        if (c + 1 < nk) {
            #pragma unroll
            for (int i = 0; i < 2; i++) {
                o0[i] = *(const float4*)(O0 + (c+1)*32 + 4*i);
                o1[i] = *(const float4*)(O1 + (c+1)*32 + 4*i);
            }
            const float* Bp2 = Bp + (size_t)(c + 1) * 32 * DIMM;
            #pragma unroll
            for (int i = 0; i < 4; i++) br[i] = *(const float4*)(Bp2 + 4*i);
        }
        #pragma unroll
        for (int kk = 0; kk < 32; kk += 8) {
            unsigned a[4], b[8][2];
            a[0] = uu(As[kk+qid  ][wm+grp  ]);
            a[1] = uu(As[kk+qid  ][wm+grp+8]);
            a[2] = uu(As[kk+qid+4][wm+grp  ]);
            a[3] = uu(As[kk+qid+4][wm+grp+8]);
            #pragma unroll
            for (int j = 0; j < 8; j++) {
                b[j][0] = uu(Bsb[kk+qid  ][wn+8*j+grp]);
                b[j][1] = uu(Bsb[kk+qid+4][wn+8*j+grp]);
            }
            #pragma unroll
            for (int j = 0; j < 8; j++) mma8(acc[j], a, b[j]);
        }
        __syncthreads();
    }
    #pragma unroll
    for (int j = 0; j < 8; j++) {
        const int col = wn + 8*j + 2*qid;
        atomicAdd(&C[(size_t)(wm+grp  ) * DIMM + col    ], acc[j][0]);
        atomicAdd(&C[(size_t)(wm+grp  ) * DIMM + col + 1], acc[j][1]);
        atomicAdd(&C[(size_t)(wm+grp+8) * DIMM + col    ], acc[j][2]);
        atomicAdd(&C[(size_t)(wm+grp+8) * DIMM + col + 1], acc[j][3]);
    }
}

// ---------------------------------------------------------------------------

extern "C" void kernel_launch(void* const* d_in, const int* in_sizes, int n_in,
                              void* d_out, int out_size)
{
    const float* tensor  = (const float*)d_in[0];
    const float* latents = (const float*)d_in[1];
    const float* Wq      = (const float*)d_in[2];
    const float* Wkv     = (const float*)d_in[3];
    const float* Wo      = (const float*)d_in[4];
    float*       out     = (float*)d_out;

    (void)in_sizes; (void)n_in; (void)out_size;

    cudaFuncSetAttribute(k_flash, cudaFuncAttributeMaxDynamicSharedMemorySize, FLASH_SMEM);

    k_prep_part <<<288, 256>>>(Wq, Wkv, Wo, out);
    k_prep_red  <<<256, 256>>>();
    k_flash     <<<BTT * HEADS, 512, FLASH_SMEM>>>(tensor, latents);
    k_final_part<<<dim3(2 * HEADS, BTT), 256>>>(out);
}